// round 16
// baseline (speedup 1.0000x reference)
#include <cuda_runtime.h>
#include <cuda_fp16.h>
#include <math.h>
#include <stdint.h>

#define T_TOK 8192
#define D_DIM 1024
#define F_DIM 4096
#define E_EXP 8

// ---------------- scratch (static device globals; no allocations) ----------
__device__ int    g_cnt[E_EXP];
__device__ int    g_tok[E_EXP * T_TOK];
__device__ float  g_wt [E_EXP * T_TOK];

__device__ __half g_xh [(size_t)T_TOK * D_DIM];
__device__ __half g_w1h[(size_t)E_EXP * F_DIM * D_DIM];
__device__ __half g_w2h[(size_t)E_EXP * D_DIM * F_DIM];
__device__ __half g_hh [(size_t)2 * T_TOK * F_DIM];

// ---------------- PTX helpers (sm_80+ features only) ------------------------
__device__ __forceinline__ uint32_t smem_u32(const void* p) {
    uint32_t a;
    asm("{ .reg .u64 t; cvta.to.shared.u64 t, %1; cvt.u32.u64 %0, t; }" : "=r"(a) : "l"(p));
    return a;
}
#define CP16(dst, src) asm volatile("cp.async.cg.shared.global [%0], [%1], 16;" :: "r"(dst), "l"(src) : "memory")
#define LDX4(r, a)                                                             \
    asm volatile("ldmatrix.sync.aligned.m8n8.x4.shared.b16 {%0,%1,%2,%3}, [%4];" \
        : "=r"((r)[0]), "=r"((r)[1]), "=r"((r)[2]), "=r"((r)[3]) : "r"(a))
#define MMAH(d, a, b0, b1)                                                     \
    asm volatile("mma.sync.aligned.m16n8k16.row.col.f32.f16.f16.f32 "          \
        "{%0,%1,%2,%3},{%4,%5,%6,%7},{%8,%9},{%0,%1,%2,%3};"                   \
        : "+f"((d)[0]), "+f"((d)[1]), "+f"((d)[2]), "+f"((d)[3])               \
        : "r"((a)[0]), "r"((a)[1]), "r"((a)[2]), "r"((a)[3]), "r"(b0), "r"(b1))

// mbarrier flow control (sm_80 mbarrier + cp.async integration)
#define MB_INIT(mb, c)  asm volatile("mbarrier.init.shared.b64 [%0], %1;" :: "r"(mb), "r"(c) : "memory")
#define MB_ARRIVE(mb)   asm volatile("mbarrier.arrive.shared.b64 _, [%0];" :: "r"(mb) : "memory")
#define CP_ARRIVE(mb)   asm volatile("cp.async.mbarrier.arrive.noinc.shared.b64 [%0];" :: "r"(mb) : "memory")
#define MBAR_WAIT(mb, par) do {                                                \
    uint32_t _m = (mb); uint32_t _p = (par); uint32_t _d;                      \
    asm volatile("{ .reg .pred p; mbarrier.try_wait.parity.acquire.cta.shared::cta.b64 p, [%1], %2; selp.b32 %0, 1, 0, p; }" \
        : "=r"(_d) : "r"(_m), "r"(_p) : "memory");                             \
    if (!_d) {                                                                 \
        asm volatile("{ .reg .pred P1; WL%=: mbarrier.try_wait.parity.acquire.cta.shared::cta.b64 P1, [%0], %1, 0x989680;" \
            " @P1 bra.uni WD%=; bra.uni WL%=; WD%=: }" :: "r"(_m), "r"(_p) : "memory"); \
    } } while (0)
// Relaxed wait: producer-side only — post-wait accesses are async-proxy.
#define MBAR_WAIT_RLX(mb, par) do {                                            \
    uint32_t _m = (mb); uint32_t _p = (par); uint32_t _d;                      \
    asm volatile("{ .reg .pred p; mbarrier.try_wait.parity.relaxed.cta.shared::cta.b64 p, [%1], %2; selp.b32 %0, 1, 0, p; }" \
        : "=r"(_d) : "r"(_m), "r"(_p) : "memory");                             \
    if (!_d) {                                                                 \
        asm volatile("{ .reg .pred P1; WL%=: mbarrier.try_wait.parity.relaxed.cta.shared::cta.b64 P1, [%0], %1, 0x989680;" \
            " @P1 bra.uni WD%=; bra.uni WL%=; WD%=: }" :: "r"(_m), "r"(_p) : "memory"); \
    } } while (0)

__device__ __forceinline__ uint32_t pack_h(__half a, __half b) {
    return ((uint32_t)__half_as_ushort(b) << 16) | __half_as_ushort(a);
}

// SMEM: toks @0 (512B), bias @512 (512B), wts @1024 (512B),
//       mbar full[3] @1536, empty[3] @1560, stages @2048.
// Stage (k-chunk 64 fp16 = 128B, pitch 144B): A @0 (128x144), B @18432.
// 3-stage ring: 2048 + 3*36864 = 112640 B/CTA -> 2 CTAs/SM.
#define SM_HDR  2048
#define PITCH   144
#define STG_SZ  36864
#define SMEM_DYN (SM_HDR + 3 * STG_SZ)
// fc1 epilogue staging pitch: 272B = 17*16 (uint4-aligned, conflict-free).
#define EPI_PITCH 272

// ---------------- fused init + convert + gate --------------------------------
__global__ void k_split(const float* __restrict__ x, const float* __restrict__ gw,
                        const float* __restrict__ w1, const float* __restrict__ w2,
                        float4* __restrict__ out4, float* __restrict__ probs_out) {
    size_t stride = (size_t)gridDim.x * blockDim.x;
    size_t i0 = (size_t)blockIdx.x * blockDim.x + threadIdx.x;
    if (i0 < E_EXP) g_cnt[i0] = 0;

    // ---- gating: one warp per token (identical FP sequence since R1) ----
    {
        int warp = (int)(i0 >> 5);
        int lane = threadIdx.x & 31;
        if (warp < T_TOK) {
            const float* xr = x + (size_t)warp * D_DIM;
            float acc[E_EXP];
#pragma unroll
            for (int e = 0; e < E_EXP; e++) acc[e] = 0.f;
            for (int k = lane * 4; k < D_DIM; k += 128) {
                float4 xv = *(const float4*)(xr + k);
#pragma unroll
                for (int e = 0; e < E_EXP; e++) {
                    float4 wv = *(const float4*)(gw + (size_t)e * D_DIM + k);
                    acc[e] += xv.x * wv.x + xv.y * wv.y + xv.z * wv.z + xv.w * wv.w;
                }
            }
#pragma unroll
            for (int e = 0; e < E_EXP; e++)
#pragma unroll
                for (int o = 16; o > 0; o >>= 1)
                    acc[e] += __shfl_xor_sync(0xffffffffu, acc[e], o);
            if (lane == 0) {
                float mx = acc[0];
#pragma unroll
                for (int e = 1; e < E_EXP; e++) mx = fmaxf(mx, acc[e]);
                float p[E_EXP], s = 0.f;
#pragma unroll
                for (int e = 0; e < E_EXP; e++) { p[e] = expf(acc[e] - mx); s += p[e]; }
                float inv = 1.f / s;
#pragma unroll
                for (int e = 0; e < E_EXP; e++) {
                    p[e] *= inv;
                    probs_out[(size_t)warp * E_EXP + e] = p[e];
                }
                int j0 = 0;
#pragma unroll
                for (int e = 1; e < E_EXP; e++) if (p[e] > p[j0]) j0 = e;
                int j1 = (j0 == 0) ? 1 : 0;
#pragma unroll
                for (int e = 0; e < E_EXP; e++) if (e != j0 && p[e] > p[j1]) j1 = e;
                float denom = p[j0] + p[j1] + 1e-9f;
                int s0 = atomicAdd(&g_cnt[j0], 1);
                g_tok[j0 * T_TOK + s0] = warp; g_wt[j0 * T_TOK + s0] = p[j0] / denom;
                int s1 = atomicAdd(&g_cnt[j1], 1);
                g_tok[j1 * T_TOK + s1] = warp; g_wt[j1 * T_TOK + s1] = p[j1] / denom;
            }
        }
    }

    // ---- out zero (uint4 granules, 2-way) ----
    const size_t no4 = (size_t)T_TOK * D_DIM / 4;
    float4 z = make_float4(0.f, 0.f, 0.f, 0.f);
    for (size_t i = i0; i < no4; i += 2 * stride) {
        out4[i] = z;
        if (i + stride < no4) out4[i + stride] = z;
    }

    // ---- fp32 -> fp16 converts: uint4 out-granule (2x float4 in), 2-way unroll
    //      => 4 independent 16B loads in flight per thread per iteration.
    const size_t nx8 = (size_t)T_TOK * D_DIM / 8;            // 1M, divides stride
    const size_t nw8 = (size_t)E_EXP * F_DIM * D_DIM / 8;    // 4M, divides stride
    uint4* xo  = (uint4*)g_xh;
    uint4* w1o = (uint4*)g_w1h;
    uint4* w2o = (uint4*)g_w2h;
#define CVT8(dst, src, n) for (size_t i = i0; i < (n); i += 2 * stride) {      \
        const float4* s4 = (const float4*)(src);                               \
        float4 a0 = s4[2 * i], a1 = s4[2 * i + 1];                             \
        float4 b0 = s4[2 * (i + stride)], b1 = s4[2 * (i + stride) + 1];       \
        (dst)[i] = make_uint4(                                                 \
            pack_h(__float2half_rn(a0.x), __float2half_rn(a0.y)),              \
            pack_h(__float2half_rn(a0.z), __float2half_rn(a0.w)),              \
            pack_h(__float2half_rn(a1.x), __float2half_rn(a1.y)),              \
            pack_h(__float2half_rn(a1.z), __float2half_rn(a1.w)));             \
        (dst)[i + stride] = make_uint4(                                        \
            pack_h(__float2half_rn(b0.x), __float2half_rn(b0.y)),              \
            pack_h(__float2half_rn(b0.z), __float2half_rn(b0.w)),              \
            pack_h(__float2half_rn(b1.x), __float2half_rn(b1.y)),              \
            pack_h(__float2half_rn(b1.z), __float2half_rn(b1.w)));             \
    }
    // n is an exact multiple of 2*stride (1M / 4M vs 512K) -> no bounds checks.
    CVT8(xo,  x,  nx8);
    CVT8(w1o, w1, nw8);
    CVT8(w2o, w2, nw8);
}

// ---------------- inline prefix over 8 counters ------------------------------
__device__ __forceinline__ int expert_off(int e) {
    int off = 0;
#pragma unroll
    for (int i = 0; i < E_EXP - 1; ++i)
        if (i < e) off += g_cnt[i];
    return off;
}

// ---------------- GEMM core: block 128x128xk64, 8 warps, warp 32x64 ---------
#define LDM_SETUP()                                                            \
    const int lane = tid & 31, wid = tid >> 5;                                 \
    const int wm = (wid & 3) * 32, wn = (wid >> 2) * 64;                       \
    uint32_t aav[2];                                                           \
    _Pragma("unroll") for (int mt = 0; mt < 2; ++mt)                           \
        aav[mt] = sb + SM_HDR + (wm + mt * 16 + (lane & 15)) * PITCH +         \
                  ((lane >> 4) & 1) * 16;                                      \
    uint32_t bbv[4];                                                           \
    _Pragma("unroll") for (int g = 0; g < 4; ++g)                              \
        bbv[g] = sb + SM_HDR + 18432 +                                         \
            (wn + g * 16 + (lane & 7) + ((lane >> 4) & 1) * 8) * PITCH +       \
            ((lane >> 3) & 1) * 16;                                            \
    const uint32_t mbF0 = sb + 1536, mbF1 = sb + 1544, mbF2 = sb + 1552;       \
    const uint32_t mbE0 = sb + 1560, mbE1 = sb + 1568, mbE2 = sb + 1576;       \
    (void)mbF0; (void)mbF1; (void)mbF2; (void)mbE0; (void)mbE1; (void)mbE2;

// Fragment-pipelined chunk (validated R8): bit-identical per-accumulator order.
#define CHUNK(so) {                                                            \
    uint32_t Ah[2][2][4], Bh[2][4];                                            \
    LDX4(Ah[0][0], aav[0] + (so));                                             \
    LDX4(Ah[0][1], aav[1] + (so));                                             \
    LDX4(Bh[0], bbv[0] + (so));                                                \
    _Pragma("unroll") for (int kk = 0; kk < 4; ++kk) {                         \
        _Pragma("unroll") for (int g = 0; g < 4; ++g) {                        \
            const int cur = g & 1, nxt = cur ^ 1;                              \
            if (g < 3)       { LDX4(Bh[nxt], bbv[g + 1] + (so) + kk * 32); }   \
            else if (kk < 3) { LDX4(Bh[nxt], bbv[0] + (so) + (kk + 1) * 32); } \
            if (g == 0 && kk < 3) {                                            \
                LDX4(Ah[(kk + 1) & 1][0], aav[0] + (so) + (kk + 1) * 32);      \
                LDX4(Ah[(kk + 1) & 1][1], aav[1] + (so) + (kk + 1) * 32);      \
            }                                                                  \
            MMAH(acc[0][2 * g],     Ah[kk & 1][0], Bh[cur][0], Bh[cur][1]);    \
            MMAH(acc[1][2 * g],     Ah[kk & 1][1], Bh[cur][0], Bh[cur][1]);    \
            MMAH(acc[0][2 * g + 1], Ah[kk & 1][0], Bh[cur][2], Bh[cur][3]);    \
            MMAH(acc[1][2 * g + 1], Ah[kk & 1][1], Bh[cur][2], Bh[cur][3]);    \
        }                                                                      \
    }                                                                          \
}

#define ACC_INIT()                                                             \
    float acc[2][8][4];                                                        \
    _Pragma("unroll") for (int i = 0; i < 2; i++)                              \
        _Pragma("unroll") for (int j = 0; j < 8; j++)                          \
            _Pragma("unroll") for (int k = 0; k < 4; k++) acc[i][j][k] = 0.f;

// Consumer-first mbarrier ring iteration (schedule validated R12/R13).
#define MB_ITER(STAGE, cc, J, JS, PF, PE)                                      \
    if ((cc) < NC) {                                                           \
        MBAR_WAIT(mbF##J, PF);                                                 \
        CHUNK((J) * STG_SZ);                                                   \
        if (lane == 0) MB_ARRIVE(mbE##J);                                      \
        if ((cc) + 2 < NC) {                                                   \
            if ((cc) >= 1) MBAR_WAIT_RLX(mbE##JS, PE);                         \
            STAGE((cc) + 2, (JS) * STG_SZ);                                    \
            CP_ARRIVE(mbF##JS);                                                \
        }                                                                      \
    }

#define MB_LOOP(STAGE)                                                         \
    for (int cb = 0; cb < NC; cb += 6) {                                       \
        MB_ITER(STAGE, cb + 0, 0, 2, 0, 1);                                    \
        MB_ITER(STAGE, cb + 1, 1, 0, 0, 0);                                    \
        MB_ITER(STAGE, cb + 2, 2, 1, 0, 0);                                    \
        MB_ITER(STAGE, cb + 3, 0, 2, 1, 0);                                    \
        MB_ITER(STAGE, cb + 4, 1, 0, 1, 1);                                    \
        MB_ITER(STAGE, cb + 5, 2, 1, 1, 1);                                    \
    }

// ---------------- fc1: h = gelu(X[gather] @ W1e^T + b1) -> fp16 -------------
__global__ __launch_bounds__(256, 2) void k_fc1_h(const float* __restrict__ b1) {
    const int e = blockIdx.z;
    const int cnt = g_cnt[e];
    const int m0 = blockIdx.y * 128;
    if (m0 >= cnt) return;
    const int n0 = blockIdx.x * 128;

    extern __shared__ __align__(128) char smp[];
    const uint32_t sb = smem_u32(smp);
    int*   toks_s = (int*)smp;
    float* bias_s = (float*)(smp + 512);
    const int tid = threadIdx.x;
    if (tid < 128) {
        toks_s[tid] = g_tok[e * T_TOK + min(m0 + tid, cnt - 1)];
        bias_s[tid] = b1[e * F_DIM + n0 + tid];
    }
    if (tid == 0) {
#pragma unroll
        for (int j = 0; j < 3; ++j) {
            MB_INIT(sb + 1536 + j * 8, 256);
            MB_INIT(sb + 1560 + j * 8, 8);
        }
    }
    __syncthreads();

    const int q = tid & 7, r = tid >> 3;
    const uint32_t dA = sb + SM_HDR + r * PITCH + q * 16;
    const uint32_t dB = dA + 18432;
    const char* xp = (const char*)g_xh;
    size_t aoff[4];
    const char* wp[4];
#pragma unroll
    for (int j = 0; j < 4; ++j) {
        aoff[j] = (size_t)toks_s[r + 32 * j] * (D_DIM * 2) + q * 16;
        wp[j] = (const char*)(g_w1h + ((size_t)e * F_DIM + n0 + r + 32 * j) * D_DIM) + q * 16;
    }

#define STAGE1(c, so) { const uint32_t ko = (uint32_t)(c) * 128;               \
    _Pragma("unroll") for (int j = 0; j < 4; ++j) {                            \
        CP16(dA + (so) + j * (32 * PITCH), xp + aoff[j] + ko);                 \
        CP16(dB + (so) + j * (32 * PITCH), wp[j] + ko);                        \
    } }

    LDM_SETUP();
    ACC_INIT();

    const int NC = D_DIM / 64;  // 16
    STAGE1(0, 0);          CP_ARRIVE(mbF0);
    STAGE1(1, STG_SZ);     CP_ARRIVE(mbF1);
    MB_LOOP(STAGE1);

    // epilogue: bias + exact gelu -> fp16 -> smem staging -> coalesced g_hh
    __syncthreads();
    const int gid2 = lane >> 2, tg = lane & 3;
#pragma unroll
    for (int mt = 0; mt < 2; ++mt)
#pragma unroll
        for (int nt = 0; nt < 8; ++nt) {
            const int n = wn + nt * 8 + tg * 2;
            const float bv0 = bias_s[n], bv1 = bias_s[n + 1];
#pragma unroll
            for (int h = 0; h < 2; ++h) {
                const int m = wm + mt * 16 + gid2 + h * 8;
                float v0 = acc[mt][nt][2 * h + 0] + bv0;
                float v1 = acc[mt][nt][2 * h + 1] + bv1;
                v0 = 0.5f * v0 * (1.f + erff(v0 * 0.7071067811865476f));
                v1 = 0.5f * v1 * (1.f + erff(v1 * 0.7071067811865476f));
                *(uint32_t*)(smp + SM_HDR + m * EPI_PITCH + n * 2) =
                    pack_h(__float2half_rn(v0), __float2half_rn(v1));
            }
        }
    __syncthreads();
    const int hbase = expert_off(e) + m0;
    uint4* gh4 = (uint4*)g_hh;
    for (int idx = tid; idx < 128 * 16; idx += 256) {
        const int row = idx >> 4, col = idx & 15;
        if (m0 + row < cnt) {
            uint4 v = *(const uint4*)(smp + SM_HDR + row * EPI_PITCH + col * 16);
            gh4[((size_t)(hbase + row) * F_DIM + n0) / 8 + col] = v;
        }
    }
}

// ---------------- fc2: out[tok] += w * (H @ W2e^T + b2) ---------------------
__global__ __launch_bounds__(256, 2) void k_fc2_h(const float* __restrict__ b2,
                                                  float* __restrict__ out) {
    const int e = blockIdx.z;
    const int cnt = g_cnt[e];
    const int m0 = blockIdx.y * 128;
    if (m0 >= cnt) return;
    const int n0 = blockIdx.x * 128;

    extern __shared__ __align__(128) char smp[];
    const uint32_t sb = smem_u32(smp);
    int*   toks_s = (int*)smp;
    float* bias_s = (float*)(smp + 512);
    float* wts_s  = (float*)(smp + 1024);
    const int tid = threadIdx.x;
    if (tid < 128) {
        const int sl = min(m0 + tid, cnt - 1);
        toks_s[tid] = g_tok[e * T_TOK + sl];
        wts_s[tid]  = g_wt [e * T_TOK + sl];
        bias_s[tid] = b2[e * D_DIM + n0 + tid];
    }
    if (tid == 0) {
#pragma unroll
        for (int j = 0; j < 3; ++j) {
            MB_INIT(sb + 1536 + j * 8, 256);
            MB_INIT(sb + 1560 + j * 8, 8);
        }
    }
    __syncthreads();

    const int q = tid & 7, r = tid >> 3;
    const uint32_t dA = sb + SM_HDR + r * PITCH + q * 16;
    const uint32_t dB = dA + 18432;
    const char* hp = (const char*)g_hh;
    const int off = expert_off(e);
    size_t aoff[4];
    const char* wp[4];
#pragma unroll
    for (int j = 0; j < 4; ++j) {
        aoff[j] = (size_t)(off + min(m0 + r + 32 * j, cnt - 1)) * (F_DIM * 2) + q * 16;
        wp[j] = (const char*)(g_w2h + ((size_t)e * D_DIM + n0 + r + 32 * j) * F_DIM) + q * 16;
    }

#define STAGE2(c, so) { const uint32_t ko = (uint32_t)(c) * 128;               \
    _Pragma("unroll") for (int j = 0; j < 4; ++j) {                            \
        CP16(dA + (so) + j * (32 * PITCH), hp + aoff[j] + ko);                 \
        CP16(dB + (so) + j * (32 * PITCH), wp[j] + ko);                        \
    } }

    LDM_SETUP();
    ACC_INIT();

    const int NC = F_DIM / 64;  // 64
    STAGE2(0, 0);          CP_ARRIVE(mbF0);
    STAGE2(1, STG_SZ);     CP_ARRIVE(mbF1);
    MB_LOOP(STAGE2);

    // epilogue: (acc + bias) * wt -> atomicAdd scatter (2 adds/elem onto 0)
    const int gid2 = lane >> 2, tg = lane & 3;
#pragma unroll
    for (int mt = 0; mt < 2; ++mt)
#pragma unroll
        for (int nt = 0; nt < 8; ++nt) {
            const int n = wn + nt * 8 + tg * 2;
            const float bv0 = bias_s[n], bv1 = bias_s[n + 1];
#pragma unroll
            for (int h = 0; h < 2; ++h) {
                const int m = wm + mt * 16 + gid2 + h * 8;
                if (m0 + m < cnt) {
                    const int   t = toks_s[m];
                    const float w = wts_s[m];
                    float* op = out + (size_t)t * D_DIM + n0 + n;
                    atomicAdd(op,     (acc[mt][nt][2 * h + 0] + bv0) * w);
                    atomicAdd(op + 1, (acc[mt][nt][2 * h + 1] + bv1) * w);
                }
            }
        }
}

// ---------------- launch -----------------------------------------------------
extern "C" void kernel_launch(void* const* d_in, const int* in_sizes, int n_in,
                              void* d_out, int out_size) {
    const float* x  = (const float*)d_in[0];
    const float* gw = (const float*)d_in[1];
    const float* w1 = (const float*)d_in[2];
    const float* b1 = (const float*)d_in[3];
    const float* w2 = (const float*)d_in[4];
    const float* b2 = (const float*)d_in[5];
    float* out   = (float*)d_out;
    float* probs = out + (size_t)T_TOK * D_DIM;

    cudaFuncSetAttribute(k_fc1_h, cudaFuncAttributeMaxDynamicSharedMemorySize, SMEM_DYN);
    cudaFuncSetAttribute(k_fc2_h, cudaFuncAttributeMaxDynamicSharedMemorySize, SMEM_DYN);

    k_split<<<1024, 256>>>(x, gw, w1, w2, (float4*)out, probs);
    k_fc1_h<<<dim3(F_DIM / 128, T_TOK / 128, E_EXP), 256, SMEM_DYN>>>(b1);
    k_fc2_h<<<dim3(D_DIM / 128, T_TOK / 128, E_EXP), 256, SMEM_DYN>>>(b2, out);
}